// round 1
// baseline (speedup 1.0000x reference)
#include <cuda_runtime.h>

#define Bn 4
#define Sn 2048
#define Dn 768
#define Hn 12
#define HDn 64
#define SCALE 0.125f

// Scratch (allocation-free rule: __device__ globals)
__device__ float g_Q[Bn * Hn * Sn * HDn];
__device__ float g_K[Bn * Hn * Sn * HDn];
__device__ float g_V[Bn * Hn * Sn * HDn];
__device__ float g_AO[Bn * Sn * Dn];

// ---------------------------------------------------------------------------
// Generic 128x128x8 SGEMM, 256 threads, 8x8 microtile.
// QKV=true : A = x param, epilogue scatters into g_Q/g_K/g_V ([B,H,S,HD])
// QKV=false: A = g_AO, epilogue writes C = out with bias
// ---------------------------------------------------------------------------
template <int N, bool QKV>
__global__ void __launch_bounds__(256) sgemm_kernel(
    const float* __restrict__ A, const float* __restrict__ Bw,
    const float* __restrict__ bias, float* __restrict__ C, int K)
{
    __shared__ float As[8][132];
    __shared__ float Bs[8][132];

    const int tid = threadIdx.x;
    const int bm = blockIdx.y * 128;
    const int bn = blockIdx.x * 128;
    const int tm = (tid >> 4) << 3;   // 0..120
    const int tn = (tid & 15) << 3;   // 0..120

    const int arow = tid >> 1;          // 0..127
    const int ac4  = (tid & 1) << 2;    // 0 or 4
    const int brow = tid >> 5;          // 0..7
    const int bc4  = (tid & 31) << 2;   // 0..124

    const float* Ap = (QKV ? A : (const float*)g_AO) + (size_t)(bm + arow) * K + ac4;
    const float* Bp = Bw + (size_t)brow * N + bn + bc4;

    float acc[8][8];
#pragma unroll
    for (int i = 0; i < 8; i++)
#pragma unroll
        for (int j = 0; j < 8; j++) acc[i][j] = 0.f;

    for (int k0 = 0; k0 < K; k0 += 8) {
        float4 a4 = *(const float4*)Ap;
        As[ac4 + 0][arow] = a4.x;
        As[ac4 + 1][arow] = a4.y;
        As[ac4 + 2][arow] = a4.z;
        As[ac4 + 3][arow] = a4.w;
        *(float4*)&Bs[brow][bc4] = *(const float4*)Bp;
        __syncthreads();

#pragma unroll
        for (int kk = 0; kk < 8; kk++) {
            float af[8], bf[8];
            *(float4*)(af)     = *(float4*)&As[kk][tm];
            *(float4*)(af + 4) = *(float4*)&As[kk][tm + 4];
            *(float4*)(bf)     = *(float4*)&Bs[kk][tn];
            *(float4*)(bf + 4) = *(float4*)&Bs[kk][tn + 4];
#pragma unroll
            for (int i = 0; i < 8; i++)
#pragma unroll
                for (int j = 0; j < 8; j++) acc[i][j] += af[i] * bf[j];
        }
        __syncthreads();
        Ap += 8;
        Bp += (size_t)8 * N;
    }

    const int col0 = bn + tn;
    float bv[8];
#pragma unroll
    for (int j = 0; j < 8; j++) bv[j] = bias[col0 + j];

    if (QKV) {
        // col -> (part, h, d); 8 consecutive cols stay inside one head (8 | 64)
        const int part = col0 / Dn;
        const int rem  = col0 - part * Dn;
        const int hh   = rem >> 6;
        const int d0   = rem & 63;
        float* dst = (part == 0) ? g_Q : ((part == 1) ? g_K : g_V);
#pragma unroll
        for (int i = 0; i < 8; i++) {
            const int row  = bm + tm + i;
            const int bidx = row >> 11;          // / 2048
            const int s    = row & 2047;
            float v[8];
#pragma unroll
            for (int j = 0; j < 8; j++) v[j] = acc[i][j] + bv[j];
            size_t base = (((size_t)(bidx * Hn + hh) * Sn) + s) * HDn + d0;
            *(float4*)(dst + base)     = *(float4*)(v);
            *(float4*)(dst + base + 4) = *(float4*)(v + 4);
        }
    } else {
#pragma unroll
        for (int i = 0; i < 8; i++) {
            const int row = bm + tm + i;
            float v[8];
#pragma unroll
            for (int j = 0; j < 8; j++) v[j] = acc[i][j] + bv[j];
            float* dst = C + (size_t)row * N + col0;
            *(float4*)(dst)     = *(float4*)(v);
            *(float4*)(dst + 4) = *(float4*)(v + 4);
        }
    }
}

// ---------------------------------------------------------------------------
// Flash attention, fp32. BQ=128, BK=64, HD=64. 128 threads (ty 0..15, tx 0..7),
// 8x8 microtile in both phases. Q,K stored d-major in smem (conflict-free frag
// loads); P stored [q][kc]; online softmax with per-row m/l.
// ---------------------------------------------------------------------------
#define ATTN_SMEM ((64 * 136 + 64 * 72 + 64 * 72 + 128 * 72) * 4)

__global__ void __launch_bounds__(128) attn_kernel()
{
    extern __shared__ float sm[];
    float(*Qt)[136] = (float(*)[136])sm;                              // [d][q] scaled
    float(*Kt)[72]  = (float(*)[72])(sm + 64 * 136);                  // [d][kc]
    float(*Vs)[72]  = (float(*)[72])(sm + 64 * 136 + 64 * 72);       // [kc][d]
    float(*Ps)[72]  = (float(*)[72])(sm + 64 * 136 + 2 * 64 * 72);   // [q][kc]

    const int tid = threadIdx.x;
    const int ty = tid >> 3;   // 0..15 -> q rows ty*8..+7
    const int tx = tid & 7;    // 0..7  -> cols tx*8..+7

    const int b = blockIdx.z, h = blockIdx.y, qt = blockIdx.x;
    const float* Qg = g_Q + ((size_t)(b * Hn + h) * Sn + qt * 128) * HDn;
    const float* Kg = g_K + (size_t)(b * Hn + h) * Sn * HDn;
    const float* Vg = g_V + (size_t)(b * Hn + h) * Sn * HDn;

    // Load Q tile (128 x 64), transpose to [d][q], fold in SCALE
#pragma unroll
    for (int i = 0; i < 16; i++) {
        int lin = tid + i * 128;
        int r = lin >> 4, c4 = (lin & 15) << 2;
        float4 q4 = *(const float4*)(Qg + r * 64 + c4);
        Qt[c4 + 0][r] = q4.x * SCALE;
        Qt[c4 + 1][r] = q4.y * SCALE;
        Qt[c4 + 2][r] = q4.z * SCALE;
        Qt[c4 + 3][r] = q4.w * SCALE;
    }

    float m[8], l[8], acc_o[8][8];
#pragma unroll
    for (int i = 0; i < 8; i++) {
        m[i] = -1e30f;
        l[i] = 0.f;
#pragma unroll
        for (int j = 0; j < 8; j++) acc_o[i][j] = 0.f;
    }

    for (int kt = 0; kt < Sn / 64; kt++) {
        const float* Kp = Kg + kt * 64 * 64;
        const float* Vp = Vg + kt * 64 * 64;
#pragma unroll
        for (int i = 0; i < 8; i++) {
            int lin = tid + i * 128;
            int r = lin >> 4, c4 = (lin & 15) << 2;
            float4 k4 = *(const float4*)(Kp + r * 64 + c4);
            Kt[c4 + 0][r] = k4.x;
            Kt[c4 + 1][r] = k4.y;
            Kt[c4 + 2][r] = k4.z;
            Kt[c4 + 3][r] = k4.w;
            *(float4*)&Vs[r][c4] = *(const float4*)(Vp + r * 64 + c4);
        }
        __syncthreads();

        // Phase A: S = (Q*scale) @ K^T   (128 x 64)
        float s[8][8];
#pragma unroll
        for (int i = 0; i < 8; i++)
#pragma unroll
            for (int j = 0; j < 8; j++) s[i][j] = 0.f;

#pragma unroll 8
        for (int d = 0; d < 64; d++) {
            float af[8], bf[8];
            *(float4*)(af)     = *(float4*)&Qt[d][ty * 8];
            *(float4*)(af + 4) = *(float4*)&Qt[d][ty * 8 + 4];
            *(float4*)(bf)     = *(float4*)&Kt[d][tx * 8];
            *(float4*)(bf + 4) = *(float4*)&Kt[d][tx * 8 + 4];
#pragma unroll
            for (int i = 0; i < 8; i++)
#pragma unroll
                for (int j = 0; j < 8; j++) s[i][j] += af[i] * bf[j];
        }

        // Online softmax (row stats reduced over tx via width-8 shuffles)
#pragma unroll
        for (int i = 0; i < 8; i++) {
            float rmax = s[i][0];
#pragma unroll
            for (int j = 1; j < 8; j++) rmax = fmaxf(rmax, s[i][j]);
            rmax = fmaxf(rmax, __shfl_xor_sync(0xffffffffu, rmax, 1, 8));
            rmax = fmaxf(rmax, __shfl_xor_sync(0xffffffffu, rmax, 2, 8));
            rmax = fmaxf(rmax, __shfl_xor_sync(0xffffffffu, rmax, 4, 8));
            float mn = fmaxf(m[i], rmax);
            float corr = __expf(m[i] - mn);
            m[i] = mn;
            float rs = 0.f;
#pragma unroll
            for (int j = 0; j < 8; j++) {
                s[i][j] = __expf(s[i][j] - mn);
                rs += s[i][j];
            }
            rs += __shfl_xor_sync(0xffffffffu, rs, 1, 8);
            rs += __shfl_xor_sync(0xffffffffu, rs, 2, 8);
            rs += __shfl_xor_sync(0xffffffffu, rs, 4, 8);
            l[i] = l[i] * corr + rs;
#pragma unroll
            for (int j = 0; j < 8; j++) acc_o[i][j] *= corr;
            *(float4*)&Ps[ty * 8 + i][tx * 8]     = make_float4(s[i][0], s[i][1], s[i][2], s[i][3]);
            *(float4*)&Ps[ty * 8 + i][tx * 8 + 4] = make_float4(s[i][4], s[i][5], s[i][6], s[i][7]);
        }
        __syncwarp();   // P rows are produced+consumed within one warp

        // Phase B: O += P @ V   (128 x 64)
#pragma unroll 8
        for (int kc = 0; kc < 64; kc++) {
            float af[8];
#pragma unroll
            for (int i = 0; i < 8; i++) af[i] = Ps[ty * 8 + i][kc];
            float bf[8];
            *(float4*)(bf)     = *(float4*)&Vs[kc][tx * 8];
            *(float4*)(bf + 4) = *(float4*)&Vs[kc][tx * 8 + 4];
#pragma unroll
            for (int i = 0; i < 8; i++)
#pragma unroll
                for (int j = 0; j < 8; j++) acc_o[i][j] += af[i] * bf[j];
        }
        __syncthreads();   // before next tile overwrites Kt/Vs (and Ps reuse)
    }

    // Normalize and write to g_AO in [B,S,H*HD] layout (ready for out-proj)
#pragma unroll
    for (int i = 0; i < 8; i++) {
        float inv = 1.0f / l[i];
        int q = qt * 128 + ty * 8 + i;
        float* dst = g_AO + ((size_t)(b * Sn + q)) * Dn + h * 64 + tx * 8;
        float4 o0 = make_float4(acc_o[i][0] * inv, acc_o[i][1] * inv,
                                acc_o[i][2] * inv, acc_o[i][3] * inv);
        float4 o1 = make_float4(acc_o[i][4] * inv, acc_o[i][5] * inv,
                                acc_o[i][6] * inv, acc_o[i][7] * inv);
        *(float4*)dst = o0;
        *(float4*)(dst + 4) = o1;
    }
}

// ---------------------------------------------------------------------------
extern "C" void kernel_launch(void* const* d_in, const int* in_sizes, int n_in,
                              void* d_out, int out_size)
{
    const float* x     = (const float*)d_in[0];
    const float* w_qkv = (const float*)d_in[1];
    const float* b_qkv = (const float*)d_in[2];
    const float* w_out = (const float*)d_in[3];
    const float* b_out = (const float*)d_in[4];
    float* out = (float*)d_out;

    (void)in_sizes; (void)n_in; (void)out_size;

    cudaFuncSetAttribute(attn_kernel,
                         cudaFuncAttributeMaxDynamicSharedMemorySize, ATTN_SMEM);

    // 1) fused QKV projection + scatter to [B,H,S,HD]
    sgemm_kernel<3 * Dn, true><<<dim3((3 * Dn) / 128, (Bn * Sn) / 128), 256>>>(
        x, w_qkv, b_qkv, nullptr, Dn);

    // 2) flash attention
    attn_kernel<<<dim3(Sn / 128, Hn, Bn), 128, ATTN_SMEM>>>();

    // 3) output projection
    sgemm_kernel<Dn, false><<<dim3(Dn / 128, (Bn * Sn) / 128), 256>>>(
        nullptr, w_out, b_out, out, Dn);
}

// round 3
// speedup vs baseline: 2.9486x; 2.9486x over previous
#include <cuda_runtime.h>
#include <cstdint>

#define Bn 4
#define Sn 2048
#define Dn 768
#define Hn 12
#define HDn 64
#define SCALE 0.125f

// Scratch (allocation-free rule: __device__ globals)
__device__ float g_Q[Bn * Hn * Sn * HDn];
__device__ float g_K[Bn * Hn * Sn * HDn];
__device__ float g_V[Bn * Hn * Sn * HDn];
__device__ float g_AO[Bn * Sn * Dn];

// ---------------------------------------------------------------------------
// Helpers (base sm_100 features only: cp.async, mma.sync tf32, cvt tf32)
// ---------------------------------------------------------------------------
__device__ __forceinline__ uint32_t smem_u32(const void* p) {
    uint32_t a;
    asm("{ .reg .u64 t; cvta.to.shared.u64 t, %1; cvt.u32.u64 %0, t; }"
        : "=r"(a) : "l"(p));
    return a;
}
__device__ __forceinline__ void cp16(const void* dst, const void* src) {
    asm volatile("cp.async.cg.shared.global [%0], [%1], 16;"
                 :: "r"(smem_u32(dst)), "l"(src));
}
__device__ __forceinline__ void cp_commit() {
    asm volatile("cp.async.commit_group;" ::: "memory");
}
template <int N>
__device__ __forceinline__ void cp_wait() {
    asm volatile("cp.async.wait_group %0;" :: "n"(N) : "memory");
}
__device__ __forceinline__ uint32_t f2tf(float x) {
    uint32_t r;
    asm("cvt.rna.tf32.f32 %0, %1;" : "=r"(r) : "f"(x));
    return r;
}
// D(16x8,f32) += A(16x8,tf32) * B(8x8,tf32)
__device__ __forceinline__ void mma8(float* c, const uint32_t* a, const uint32_t* b) {
    asm volatile(
        "mma.sync.aligned.m16n8k8.row.col.f32.tf32.tf32.f32 "
        "{%0,%1,%2,%3}, {%4,%5,%6,%7}, {%8,%9}, {%0,%1,%2,%3};"
        : "+f"(c[0]), "+f"(c[1]), "+f"(c[2]), "+f"(c[3])
        : "r"(a[0]), "r"(a[1]), "r"(a[2]), "r"(a[3]), "r"(b[0]), "r"(b[1]));
}

// ---------------------------------------------------------------------------
// tf32 mma GEMM: C[M,N] = A[M,768] @ W[768,N] + bias
// 128x128 tile, 256 threads, 8 warps (2x4), warp tile 64x32, mma 16x8x8.
// Double-buffered cp.async, k-chunk 16.
// QKV=true : A = x, epilogue scatters into g_Q/g_K/g_V ([B,H,S,HD])
// QKV=false: A = g_AO, epilogue writes C (+bias)
// ---------------------------------------------------------------------------
template <int N, bool QKV>
__global__ void __launch_bounds__(256) gemm_mma(const float* __restrict__ A_in,
                                                const float* __restrict__ W,
                                                const float* __restrict__ bias,
                                                float* __restrict__ C) {
    __shared__ float As[2][128][20];   // [m][k] pad 20 -> conflict-free frags
    __shared__ float Bs[2][16][136];   // [k][n] pad 136
    __shared__ float s_bias[128];

    const int tid = threadIdx.x;
    const int lane = tid & 31, warp = tid >> 5;
    const int g = lane >> 2, t = lane & 3;
    const int m0 = (warp >> 2) * 64, n0 = (warp & 3) * 32;
    const int bm = blockIdx.y * 128, bn = blockIdx.x * 128;

    const float* Ag = QKV ? A_in : (const float*)g_AO;
    if (tid < 128) s_bias[tid] = bias[bn + tid];

    auto load_stage = [&](int st, int k0) {
#pragma unroll
        for (int i = 0; i < 2; i++) {
            int lin = tid + i * 256;
            int row = lin >> 2, c4 = (lin & 3) << 2;
            cp16(&As[st][row][c4], Ag + (size_t)(bm + row) * Dn + k0 + c4);
        }
#pragma unroll
        for (int i = 0; i < 2; i++) {
            int lin = tid + i * 256;
            int row = lin >> 5, c4 = (lin & 31) << 2;
            cp16(&Bs[st][row][c4], W + (size_t)(k0 + row) * N + bn + c4);
        }
    };

    float acc[4][4][4];
#pragma unroll
    for (int a = 0; a < 4; a++)
#pragma unroll
        for (int b = 0; b < 4; b++)
#pragma unroll
            for (int c = 0; c < 4; c++) acc[a][b][c] = 0.f;

    load_stage(0, 0);
    cp_commit();

    for (int ch = 0; ch < 48; ch++) {
        if (ch < 47) {
            load_stage((ch + 1) & 1, (ch + 1) * 16);
            cp_commit();
            cp_wait<1>();
        } else {
            cp_wait<0>();
        }
        __syncthreads();
        const int buf = ch & 1;
#pragma unroll
        for (int ks = 0; ks < 2; ks++) {
            const int kk = ks * 8;
            uint32_t af[4][4];
#pragma unroll
            for (int mb = 0; mb < 4; mb++) {
                const int r0 = m0 + mb * 16 + g;
                af[mb][0] = f2tf(As[buf][r0][kk + t]);
                af[mb][1] = f2tf(As[buf][r0 + 8][kk + t]);
                af[mb][2] = f2tf(As[buf][r0][kk + t + 4]);
                af[mb][3] = f2tf(As[buf][r0 + 8][kk + t + 4]);
            }
#pragma unroll
            for (int nb = 0; nb < 4; nb++) {
                uint32_t bf[2];
                bf[0] = f2tf(Bs[buf][kk + t][n0 + nb * 8 + g]);
                bf[1] = f2tf(Bs[buf][kk + t + 4][n0 + nb * 8 + g]);
#pragma unroll
                for (int mb = 0; mb < 4; mb++) mma8(acc[mb][nb], af[mb], bf);
            }
        }
        __syncthreads();
    }

    // Epilogue: c0/c1 -> row r0 cols 2t,2t+1 ; c2/c3 -> row r0+8
#pragma unroll
    for (int mb = 0; mb < 4; mb++) {
        const int row0 = bm + m0 + mb * 16 + g;
        const int row1 = row0 + 8;
#pragma unroll
        for (int nb = 0; nb < 4; nb++) {
            const int ci = n0 + nb * 8 + 2 * t;
            const int col0 = bn + ci;
            const float b0 = s_bias[ci], b1 = s_bias[ci + 1];
            float2 v0 = make_float2(acc[mb][nb][0] + b0, acc[mb][nb][1] + b1);
            float2 v1 = make_float2(acc[mb][nb][2] + b0, acc[mb][nb][3] + b1);
            if (QKV) {
                const int part = col0 / Dn;
                const int rem = col0 - part * Dn;
                const int hh = rem >> 6, d0 = rem & 63;
                float* dst = (part == 0) ? g_Q : ((part == 1) ? g_K : g_V);
                size_t base0 =
                    (((size_t)((row0 >> 11) * Hn + hh) * Sn) + (row0 & 2047)) * HDn + d0;
                size_t base1 =
                    (((size_t)((row1 >> 11) * Hn + hh) * Sn) + (row1 & 2047)) * HDn + d0;
                *(float2*)(dst + base0) = v0;
                *(float2*)(dst + base1) = v1;
            } else {
                *(float2*)(C + (size_t)row0 * Dn + col0) = v0;
                *(float2*)(C + (size_t)row1 * Dn + col0) = v1;
            }
        }
    }
}

// ---------------------------------------------------------------------------
// Flash attention on tf32 mma.sync. BQ=128, BK=64, HD=64.
// 128 threads = 4 warps; warp w owns q rows [w*32, w*32+32): 2 m-blocks.
// S = Q@K^T (K transposed to [d][kc] in smem), softmax on fragments,
// P round-trips smem, O += P@V.
// ---------------------------------------------------------------------------
#define ATTN_SMEM ((128 * 68 + 64 * 72 + 64 * 72 + 128 * 68) * 4)

__global__ void __launch_bounds__(128) attn_kernel() {
    extern __shared__ float sm[];
    float(*Qs)[68] = (float(*)[68])sm;                         // [q][d]
    float(*Kt)[72] = (float(*)[72])(sm + 128 * 68);            // [d][kc]
    float(*Vs)[72] = (float(*)[72])(sm + 128 * 68 + 64 * 72);  // [kc][d]
    float(*Ps)[68] = (float(*)[68])(sm + 128 * 68 + 2 * 64 * 72);  // [q][kc]

    const int tid = threadIdx.x;
    const int lane = tid & 31, warp = tid >> 5;
    const int g = lane >> 2, t = lane & 3;
    const int q0 = warp * 32;

    const int b = blockIdx.z, h = blockIdx.y, qt = blockIdx.x;
    const float* Qg = g_Q + ((size_t)(b * Hn + h) * Sn + qt * 128) * HDn;
    const float* Kg = g_K + (size_t)(b * Hn + h) * Sn * HDn;
    const float* Vg = g_V + (size_t)(b * Hn + h) * Sn * HDn;

    // async Q load [128][64] -> Qs (caught by first tile's cp_wait<0>)
#pragma unroll
    for (int i = 0; i < 16; i++) {
        int lin = tid + i * 128;
        int r = lin >> 4, c4 = (lin & 15) << 2;
        cp16(&Qs[r][c4], Qg + r * 64 + c4);
    }

    float m_[2][2], l_[2][2], oa[2][8][4];
#pragma unroll
    for (int mb = 0; mb < 2; mb++)
#pragma unroll
        for (int hf = 0; hf < 2; hf++) {
            m_[mb][hf] = -1e30f;
            l_[mb][hf] = 0.f;
        }
#pragma unroll
    for (int mb = 0; mb < 2; mb++)
#pragma unroll
        for (int nb = 0; nb < 8; nb++)
#pragma unroll
            for (int c = 0; c < 4; c++) oa[mb][nb][c] = 0.f;

    for (int kt = 0; kt < 32; kt++) {
        const float* Kp = Kg + kt * 64 * 64;
        const float* Vp = Vg + kt * 64 * 64;
        // V: async direct copy [kc][d]
#pragma unroll
        for (int i = 0; i < 8; i++) {
            int lin = tid + i * 128;
            int r = lin >> 4, c4 = (lin & 15) << 2;
            cp16(&Vs[r][c4], Vp + r * 64 + c4);
        }
        cp_commit();
        // K: transpose to [d][kc] (row r = lane -> conflict-free STS)
        {
            const int r = tid & 63, cg = tid >> 6;
#pragma unroll
            for (int j = 0; j < 8; j++) {
                const int c = cg * 32 + j * 4;
                float4 k4 = *(const float4*)(Kp + r * 64 + c);
                Kt[c + 0][r] = k4.x;
                Kt[c + 1][r] = k4.y;
                Kt[c + 2][r] = k4.z;
                Kt[c + 3][r] = k4.w;
            }
        }
        cp_wait<0>();
        __syncthreads();

        // S = Q @ K^T : per warp 2 m-blocks x 8 n-blocks
        float sf[2][8][4];
#pragma unroll
        for (int mb = 0; mb < 2; mb++)
#pragma unroll
            for (int nb = 0; nb < 8; nb++)
#pragma unroll
                for (int c = 0; c < 4; c++) sf[mb][nb][c] = 0.f;

#pragma unroll
        for (int ks = 0; ks < 8; ks++) {
            const int kk = ks * 8;
            uint32_t af[2][4];
#pragma unroll
            for (int mb = 0; mb < 2; mb++) {
                const int r0 = q0 + mb * 16 + g;
                af[mb][0] = f2tf(Qs[r0][kk + t]);
                af[mb][1] = f2tf(Qs[r0 + 8][kk + t]);
                af[mb][2] = f2tf(Qs[r0][kk + t + 4]);
                af[mb][3] = f2tf(Qs[r0 + 8][kk + t + 4]);
            }
#pragma unroll
            for (int nb = 0; nb < 8; nb++) {
                uint32_t bf[2];
                bf[0] = f2tf(Kt[kk + t][nb * 8 + g]);
                bf[1] = f2tf(Kt[kk + t + 4][nb * 8 + g]);
                mma8(sf[0][nb], af[0], bf);
                mma8(sf[1][nb], af[1], bf);
            }
        }

        // online softmax on fragments; rows: (mb, hf) -> q0+mb*16+g+8*hf
#pragma unroll
        for (int mb = 0; mb < 2; mb++)
#pragma unroll
            for (int hf = 0; hf < 2; hf++) {
                float rmax = -1e30f;
#pragma unroll
                for (int nb = 0; nb < 8; nb++) {
                    rmax = fmaxf(rmax, sf[mb][nb][2 * hf] * SCALE);
                    rmax = fmaxf(rmax, sf[mb][nb][2 * hf + 1] * SCALE);
                }
                rmax = fmaxf(rmax, __shfl_xor_sync(0xffffffffu, rmax, 1));
                rmax = fmaxf(rmax, __shfl_xor_sync(0xffffffffu, rmax, 2));
                const float mn = fmaxf(m_[mb][hf], rmax);
                const float corr = __expf(m_[mb][hf] - mn);
                m_[mb][hf] = mn;
                float rs = 0.f;
                const int row = q0 + mb * 16 + g + 8 * hf;
#pragma unroll
                for (int nb = 0; nb < 8; nb++) {
                    float p0 = __expf(sf[mb][nb][2 * hf] * SCALE - mn);
                    float p1 = __expf(sf[mb][nb][2 * hf + 1] * SCALE - mn);
                    rs += p0 + p1;
                    *(float2*)&Ps[row][nb * 8 + 2 * t] = make_float2(p0, p1);
                }
                rs += __shfl_xor_sync(0xffffffffu, rs, 1);
                rs += __shfl_xor_sync(0xffffffffu, rs, 2);
                l_[mb][hf] = l_[mb][hf] * corr + rs;
#pragma unroll
                for (int nb = 0; nb < 8; nb++) {
                    oa[mb][nb][2 * hf] *= corr;
                    oa[mb][nb][2 * hf + 1] *= corr;
                }
            }
        __syncwarp();

        // O += P @ V
#pragma unroll
        for (int ks = 0; ks < 8; ks++) {
            const int kk = ks * 8;
            uint32_t af[2][4];
#pragma unroll
            for (int mb = 0; mb < 2; mb++) {
                const int r0 = q0 + mb * 16 + g;
                af[mb][0] = f2tf(Ps[r0][kk + t]);
                af[mb][1] = f2tf(Ps[r0 + 8][kk + t]);
                af[mb][2] = f2tf(Ps[r0][kk + t + 4]);
                af[mb][3] = f2tf(Ps[r0 + 8][kk + t + 4]);
            }
#pragma unroll
            for (int nb = 0; nb < 8; nb++) {
                uint32_t bf[2];
                bf[0] = f2tf(Vs[kk + t][nb * 8 + g]);
                bf[1] = f2tf(Vs[kk + t + 4][nb * 8 + g]);
                mma8(oa[0][nb], af[0], bf);
                mma8(oa[1][nb], af[1], bf);
            }
        }
        __syncthreads();
    }

    // normalize + write to g_AO [B,S,H*HD]
#pragma unroll
    for (int mb = 0; mb < 2; mb++)
#pragma unroll
        for (int hf = 0; hf < 2; hf++) {
            const int q = qt * 128 + q0 + mb * 16 + g + 8 * hf;
            const float inv = 1.0f / l_[mb][hf];
            float* dst = g_AO + ((size_t)(b * Sn + q)) * Dn + h * 64;
#pragma unroll
            for (int nb = 0; nb < 8; nb++) {
                *(float2*)(dst + nb * 8 + 2 * t) =
                    make_float2(oa[mb][nb][2 * hf] * inv, oa[mb][nb][2 * hf + 1] * inv);
            }
        }
}

// ---------------------------------------------------------------------------
extern "C" void kernel_launch(void* const* d_in, const int* in_sizes, int n_in,
                              void* d_out, int out_size)
{
    const float* x     = (const float*)d_in[0];
    const float* w_qkv = (const float*)d_in[1];
    const float* b_qkv = (const float*)d_in[2];
    const float* w_out = (const float*)d_in[3];
    const float* b_out = (const float*)d_in[4];
    float* out = (float*)d_out;

    (void)in_sizes; (void)n_in; (void)out_size;

    cudaFuncSetAttribute(attn_kernel,
                         cudaFuncAttributeMaxDynamicSharedMemorySize, ATTN_SMEM);

    // 1) fused QKV projection (tf32 mma) + scatter to [B,H,S,HD]
    gemm_mma<3 * Dn, true><<<dim3((3 * Dn) / 128, (Bn * Sn) / 128), 256>>>(
        x, w_qkv, b_qkv, nullptr);

    // 2) flash attention (tf32 mma)
    attn_kernel<<<dim3(Sn / 128, Hn, Bn), 128, ATTN_SMEM>>>();

    // 3) output projection (tf32 mma)
    gemm_mma<Dn, false><<<dim3(Dn / 128, (Bn * Sn) / 128), 256>>>(
        nullptr, w_out, b_out, out);
}

// round 5
// speedup vs baseline: 3.5173x; 1.1929x over previous
#include <cuda_runtime.h>
#include <cstdint>

#define Bn 4
#define Sn 2048
#define Dn 768
#define Hn 12
#define HDn 64
// 0.125 * log2(e): folded into Q so softmax is pure ex2
#define QSCALE 0.1803368801111204f

// Scratch (allocation-free rule: __device__ globals). Total 96MB — proven safe.
__device__ float g_Q[Bn * Hn * Sn * HDn];    // pre-scaled by QSCALE, tf32-rounded
__device__ float g_K[Bn * Hn * Sn * HDn];    // tf32-rounded
__device__ float g_V[Bn * Hn * Sn * HDn];    // tf32-rounded
__device__ float g_AO[Bn * Sn * Dn];         // phase 1: tf32-rounded x; phase 2: attn out

// ---------------------------------------------------------------------------
// Helpers (base sm_100 features only)
// ---------------------------------------------------------------------------
__device__ __forceinline__ uint32_t smem_u32(const void* p) {
    uint32_t a;
    asm("{ .reg .u64 t; cvta.to.shared.u64 t, %1; cvt.u32.u64 %0, t; }"
        : "=r"(a) : "l"(p));
    return a;
}
__device__ __forceinline__ void cp16(const void* dst, const void* src) {
    asm volatile("cp.async.cg.shared.global [%0], [%1], 16;"
                 :: "r"(smem_u32(dst)), "l"(src));
}
__device__ __forceinline__ void cp_commit() {
    asm volatile("cp.async.commit_group;" ::: "memory");
}
template <int N>
__device__ __forceinline__ void cp_wait() {
    asm volatile("cp.async.wait_group %0;" :: "n"(N) : "memory");
}
__device__ __forceinline__ uint32_t f2tf(float x) {
    uint32_t r;
    asm("cvt.rna.tf32.f32 %0, %1;" : "=r"(r) : "f"(x));
    return r;
}
__device__ __forceinline__ float tfr(float x) { return __uint_as_float(f2tf(x)); }
__device__ __forceinline__ float ex2(float x) {
    float r;
    asm("ex2.approx.f32 %0, %1;" : "=f"(r) : "f"(x));
    return r;
}
__device__ __forceinline__ uint32_t u(float x) { return __float_as_uint(x); }
// D(16x8,f32) += A(16x8,tf32) * B(8x8,tf32)
__device__ __forceinline__ void mma8(float* c, const uint32_t* a, const uint32_t* b) {
    asm volatile(
        "mma.sync.aligned.m16n8k8.row.col.f32.tf32.tf32.f32 "
        "{%0,%1,%2,%3}, {%4,%5,%6,%7}, {%8,%9}, {%0,%1,%2,%3};"
        : "+f"(c[0]), "+f"(c[1]), "+f"(c[2]), "+f"(c[3])
        : "r"(a[0]), "r"(a[1]), "r"(a[2]), "r"(a[3]), "r"(b[0]), "r"(b[1]));
}

// ---------------------------------------------------------------------------
// Pre-pass: round fp32 -> tf32 (RNA) elementwise (x -> g_AO)
// ---------------------------------------------------------------------------
__global__ void round_tf32_kernel(const float4* __restrict__ src,
                                  float4* __restrict__ dst, int n4) {
    int i = blockIdx.x * blockDim.x + threadIdx.x;
    if (i >= n4) return;
    float4 v = src[i];
    v.x = tfr(v.x); v.y = tfr(v.y); v.z = tfr(v.z); v.w = tfr(v.w);
    dst[i] = v;
}

// ---------------------------------------------------------------------------
// tf32 mma GEMM: C[M,N] = A[M,768] @ W[768,N] + bias.
// A pre-rounded (no cvt); W raw fp32, cvt applied on B fragments only.
// 128x128 tile, 256 threads, 8 warps (2x4), warp tile 64x32, mma 16x8x8.
// 3-stage cp.async pipeline, k-chunk 16.
// QKV=true : epilogue scatters tf32-rounded Q(+scale)/K/V into [B,H,S,HD]
// QKV=false: epilogue writes C = raw fp32 (+bias)
// ---------------------------------------------------------------------------
#define GEMM_SMEM ((3 * 128 * 20 + 3 * 16 * 136 + 128) * 4)

template <int N, bool QKV>
__global__ void __launch_bounds__(256) gemm_mma(const float* __restrict__ Ag,
                                                const float* __restrict__ W,
                                                const float* __restrict__ bias,
                                                float* __restrict__ C) {
    extern __shared__ float gsm[];
    float(*As)[128][20] = (float(*)[128][20])gsm;                    // [3][128][20]
    float(*Bs)[16][136] = (float(*)[16][136])(gsm + 3 * 128 * 20);   // [3][16][136]
    float* s_bias = gsm + 3 * 128 * 20 + 3 * 16 * 136;

    const int tid = threadIdx.x;
    const int lane = tid & 31, warp = tid >> 5;
    const int g = lane >> 2, t = lane & 3;
    const int m0 = (warp >> 2) * 64, n0 = (warp & 3) * 32;
    const int bm = blockIdx.y * 128, bn = blockIdx.x * 128;

    if (tid < 128) s_bias[tid] = bias[bn + tid];

    auto load_stage = [&](int st, int k0) {
#pragma unroll
        for (int i = 0; i < 2; i++) {
            int lin = tid + i * 256;
            int row = lin >> 2, c4 = (lin & 3) << 2;
            cp16(&As[st][row][c4], Ag + (size_t)(bm + row) * Dn + k0 + c4);
        }
#pragma unroll
        for (int i = 0; i < 2; i++) {
            int lin = tid + i * 256;
            int row = lin >> 5, c4 = (lin & 31) << 2;
            cp16(&Bs[st][row][c4], W + (size_t)(k0 + row) * N + bn + c4);
        }
    };

    float acc[4][4][4];
#pragma unroll
    for (int a = 0; a < 4; a++)
#pragma unroll
        for (int b = 0; b < 4; b++)
#pragma unroll
            for (int c = 0; c < 4; c++) acc[a][b][c] = 0.f;

    load_stage(0, 0);
    cp_commit();
    load_stage(1, 16);
    cp_commit();

    for (int ch = 0; ch < 48; ch++) {
        cp_wait<1>();
        __syncthreads();
        if (ch + 2 < 48) {
            load_stage((ch + 2) % 3, (ch + 2) * 16);
            cp_commit();
        }
        const int buf = ch % 3;
#pragma unroll
        for (int ks = 0; ks < 2; ks++) {
            const int kk = ks * 8;
            uint32_t af[4][4];
#pragma unroll
            for (int mb = 0; mb < 4; mb++) {
                const int r0 = m0 + mb * 16 + g;
                af[mb][0] = u(As[buf][r0][kk + t]);
                af[mb][1] = u(As[buf][r0 + 8][kk + t]);
                af[mb][2] = u(As[buf][r0][kk + t + 4]);
                af[mb][3] = u(As[buf][r0 + 8][kk + t + 4]);
            }
#pragma unroll
            for (int nb = 0; nb < 4; nb++) {
                uint32_t bf[2];
                bf[0] = f2tf(Bs[buf][kk + t][n0 + nb * 8 + g]);
                bf[1] = f2tf(Bs[buf][kk + t + 4][n0 + nb * 8 + g]);
#pragma unroll
                for (int mb = 0; mb < 4; mb++) mma8(acc[mb][nb], af[mb], bf);
            }
        }
    }

    // Epilogue
#pragma unroll
    for (int mb = 0; mb < 4; mb++) {
        const int row0 = bm + m0 + mb * 16 + g;
        const int row1 = row0 + 8;
#pragma unroll
        for (int nb = 0; nb < 4; nb++) {
            const int ci = n0 + nb * 8 + 2 * t;
            const int col0 = bn + ci;
            const float b0 = s_bias[ci], b1 = s_bias[ci + 1];
            if (QKV) {
                const int part = col0 / Dn;
                const int rem = col0 - part * Dn;
                const int hh = rem >> 6, d0 = rem & 63;
                const float mulv = (part == 0) ? QSCALE : 1.0f;
                float2 v0 = make_float2(tfr((acc[mb][nb][0] + b0) * mulv),
                                        tfr((acc[mb][nb][1] + b1) * mulv));
                float2 v1 = make_float2(tfr((acc[mb][nb][2] + b0) * mulv),
                                        tfr((acc[mb][nb][3] + b1) * mulv));
                float* dst = (part == 0) ? g_Q : ((part == 1) ? g_K : g_V);
                size_t base0 =
                    (((size_t)((row0 >> 11) * Hn + hh) * Sn) + (row0 & 2047)) * HDn + d0;
                size_t base1 =
                    (((size_t)((row1 >> 11) * Hn + hh) * Sn) + (row1 & 2047)) * HDn + d0;
                *(float2*)(dst + base0) = v0;
                *(float2*)(dst + base1) = v1;
            } else {
                float2 v0 = make_float2(acc[mb][nb][0] + b0, acc[mb][nb][1] + b1);
                float2 v1 = make_float2(acc[mb][nb][2] + b0, acc[mb][nb][3] + b1);
                *(float2*)(C + (size_t)row0 * Dn + col0) = v0;
                *(float2*)(C + (size_t)row1 * Dn + col0) = v1;
            }
        }
    }
}

// ---------------------------------------------------------------------------
// Flash attention, tf32 mma, all inputs pre-rounded (no cvt in loops).
// BQ=256, BK=64, HD=64. 256 threads = 8 warps, warp owns 32 q rows (mb=2),
// nb=8 covers all 64 kc. K,V kept natural [kc][d]; K/V double-buffered cp.async.
// Softmax base-2 (scale folded into Q). P tf32-rounded at smem store.
// ---------------------------------------------------------------------------
#define ATTN_SMEM ((256 * 68 + 2 * 64 * 68 + 2 * 64 * 72 + 256 * 68) * 4)

__global__ void __launch_bounds__(256) attn_kernel() {
    extern __shared__ float sm[];
    float(*Qs)[68] = (float(*)[68])sm;                                    // [256][68]
    float(*Ks)[68] = (float(*)[68])(sm + 256 * 68);                       // [2*64][68]
    float(*Vs)[72] = (float(*)[72])(sm + 256 * 68 + 2 * 64 * 68);         // [2*64][72]
    float(*Ps)[68] = (float(*)[68])(sm + 256 * 68 + 2 * 64 * 68 + 2 * 64 * 72);  // [256][68]

    const int tid = threadIdx.x;
    const int lane = tid & 31, warp = tid >> 5;
    const int g = lane >> 2, t = lane & 3;
    const int q0 = warp * 32;

    const int b = blockIdx.z, h = blockIdx.y, qt = blockIdx.x;
    const float* Qg = g_Q + ((size_t)(b * Hn + h) * Sn + qt * 256) * HDn;
    const float* Kg = g_K + (size_t)(b * Hn + h) * Sn * HDn;
    const float* Vg = g_V + (size_t)(b * Hn + h) * Sn * HDn;

    auto load_kv = [&](int st, int kt2) {
        const float* Kp = Kg + (size_t)kt2 * 64 * 64;
        const float* Vp = Vg + (size_t)kt2 * 64 * 64;
#pragma unroll
        for (int i = 0; i < 4; i++) {
            int lin = tid + i * 256;
            int r = lin >> 4, c4 = (lin & 15) << 2;
            cp16(&Ks[st * 64 + r][c4], Kp + r * 64 + c4);
            cp16(&Vs[st * 64 + r][c4], Vp + r * 64 + c4);
        }
    };

    // Q tile: 256x64
#pragma unroll
    for (int i = 0; i < 16; i++) {
        int lin = tid + i * 256;
        int r = lin >> 4, c4 = (lin & 15) << 2;
        cp16(&Qs[r][c4], Qg + r * 64 + c4);
    }
    load_kv(0, 0);
    cp_commit();
    cp_wait<0>();
    __syncthreads();

    float m_[2][2], l_[2][2], oa[2][8][4];
#pragma unroll
    for (int mb = 0; mb < 2; mb++)
#pragma unroll
        for (int hf = 0; hf < 2; hf++) {
            m_[mb][hf] = -1e30f;
            l_[mb][hf] = 0.f;
        }
#pragma unroll
    for (int mb = 0; mb < 2; mb++)
#pragma unroll
        for (int nb = 0; nb < 8; nb++)
#pragma unroll
            for (int c = 0; c < 4; c++) oa[mb][nb][c] = 0.f;

    for (int kt = 0; kt < 32; kt++) {
        if (kt + 1 < 32) {
            load_kv((kt + 1) & 1, kt + 1);
            cp_commit();
        }
        const int kb = (kt & 1) * 64;

        // ---- S = Q' @ K^T  (Q' already scaled by 0.125*log2e) ----
        float sf[2][8][4];
#pragma unroll
        for (int mb = 0; mb < 2; mb++)
#pragma unroll
            for (int nb = 0; nb < 8; nb++)
#pragma unroll
                for (int c = 0; c < 4; c++) sf[mb][nb][c] = 0.f;

#pragma unroll
        for (int ks = 0; ks < 8; ks++) {
            const int kk = ks * 8;
            uint32_t af[2][4];
#pragma unroll
            for (int mb = 0; mb < 2; mb++) {
                const int r0 = q0 + mb * 16 + g;
                af[mb][0] = u(Qs[r0][kk + t]);
                af[mb][1] = u(Qs[r0 + 8][kk + t]);
                af[mb][2] = u(Qs[r0][kk + t + 4]);
                af[mb][3] = u(Qs[r0 + 8][kk + t + 4]);
            }
#pragma unroll
            for (int nb = 0; nb < 8; nb++) {
                uint32_t bf[2];
                bf[0] = u(Ks[kb + nb * 8 + g][kk + t]);
                bf[1] = u(Ks[kb + nb * 8 + g][kk + t + 4]);
                mma8(sf[0][nb], af[0], bf);
                mma8(sf[1][nb], af[1], bf);
            }
        }

        // ---- online softmax, base 2 ----
#pragma unroll
        for (int mb = 0; mb < 2; mb++)
#pragma unroll
            for (int hf = 0; hf < 2; hf++) {
                float rmax = -1e30f;
#pragma unroll
                for (int nb = 0; nb < 8; nb++) {
                    rmax = fmaxf(rmax, sf[mb][nb][2 * hf]);
                    rmax = fmaxf(rmax, sf[mb][nb][2 * hf + 1]);
                }
                rmax = fmaxf(rmax, __shfl_xor_sync(0xffffffffu, rmax, 1));
                rmax = fmaxf(rmax, __shfl_xor_sync(0xffffffffu, rmax, 2));
                const float mn = fmaxf(m_[mb][hf], rmax);
                const float corr = ex2(m_[mb][hf] - mn);
                m_[mb][hf] = mn;
                float rs = 0.f;
                const int row = q0 + mb * 16 + g + 8 * hf;
#pragma unroll
                for (int nb = 0; nb < 8; nb++) {
                    float p0 = ex2(sf[mb][nb][2 * hf] - mn);
                    float p1 = ex2(sf[mb][nb][2 * hf + 1] - mn);
                    rs += p0 + p1;
                    *(float2*)&Ps[row][nb * 8 + 2 * t] = make_float2(tfr(p0), tfr(p1));
                }
                rs += __shfl_xor_sync(0xffffffffu, rs, 1);
                rs += __shfl_xor_sync(0xffffffffu, rs, 2);
                l_[mb][hf] = l_[mb][hf] * corr + rs;
#pragma unroll
                for (int nb = 0; nb < 8; nb++) {
                    oa[mb][nb][2 * hf] *= corr;
                    oa[mb][nb][2 * hf + 1] *= corr;
                }
            }
        __syncwarp();

        // ---- O += P @ V ----
#pragma unroll
        for (int ks = 0; ks < 8; ks++) {
            const int kk = ks * 8;
            uint32_t af[2][4];
#pragma unroll
            for (int mb = 0; mb < 2; mb++) {
                const int r0 = q0 + mb * 16 + g;
                af[mb][0] = u(Ps[r0][kk + t]);
                af[mb][1] = u(Ps[r0 + 8][kk + t]);
                af[mb][2] = u(Ps[r0][kk + t + 4]);
                af[mb][3] = u(Ps[r0 + 8][kk + t + 4]);
            }
#pragma unroll
            for (int nb = 0; nb < 8; nb++) {
                uint32_t bf[2];
                bf[0] = u(Vs[kb + kk + t][nb * 8 + g]);
                bf[1] = u(Vs[kb + kk + t + 4][nb * 8 + g]);
                mma8(oa[0][nb], af[0], bf);
                mma8(oa[1][nb], af[1], bf);
            }
        }
        cp_wait<0>();     // next tile resident
        __syncthreads();  // all warps done with old buffer before next prefetch
    }

    // normalize + write tf32-rounded to g_AO [B,S,H*HD]
#pragma unroll
    for (int mb = 0; mb < 2; mb++)
#pragma unroll
        for (int hf = 0; hf < 2; hf++) {
            const int q = qt * 256 + q0 + mb * 16 + g + 8 * hf;
            const float inv = 1.0f / l_[mb][hf];
            float* dst = g_AO + ((size_t)(b * Sn + q)) * Dn + h * 64;
#pragma unroll
            for (int nb = 0; nb < 8; nb++) {
                *(float2*)(dst + nb * 8 + 2 * t) =
                    make_float2(tfr(oa[mb][nb][2 * hf] * inv),
                                tfr(oa[mb][nb][2 * hf + 1] * inv));
            }
        }
}

// ---------------------------------------------------------------------------
extern "C" void kernel_launch(void* const* d_in, const int* in_sizes, int n_in,
                              void* d_out, int out_size)
{
    const float* x     = (const float*)d_in[0];
    const float* w_qkv = (const float*)d_in[1];
    const float* b_qkv = (const float*)d_in[2];
    const float* w_out = (const float*)d_in[3];
    const float* b_out = (const float*)d_in[4];
    float* out = (float*)d_out;

    (void)in_sizes; (void)n_in; (void)out_size;

    static bool init_done = false;
    static float* ao_ptr = nullptr;
    if (!init_done) {
        cudaGetSymbolAddress((void**)&ao_ptr, g_AO);
        cudaFuncSetAttribute(attn_kernel,
                             cudaFuncAttributeMaxDynamicSharedMemorySize, ATTN_SMEM);
        cudaFuncSetAttribute(gemm_mma<3 * Dn, true>,
                             cudaFuncAttributeMaxDynamicSharedMemorySize, GEMM_SMEM);
        cudaFuncSetAttribute(gemm_mma<Dn, false>,
                             cudaFuncAttributeMaxDynamicSharedMemorySize, GEMM_SMEM);
        init_done = true;
    }

    // 0) pre-round x to tf32 into g_AO (dead until attention overwrites it)
    {
        const int n4x = Bn * Sn * Dn / 4;
        round_tf32_kernel<<<(n4x + 255) / 256, 256>>>((const float4*)x,
                                                      (float4*)ao_ptr, n4x);
    }

    // 1) fused QKV projection (A = rounded x in g_AO, W raw with B-frag cvt)
    gemm_mma<3 * Dn, true>
        <<<dim3((3 * Dn) / 128, (Bn * Sn) / 128), 256, GEMM_SMEM>>>(
            ao_ptr, w_qkv, b_qkv, nullptr);

    // 2) flash attention (overwrites g_AO with attention output)
    attn_kernel<<<dim3(Sn / 256, Hn, Bn), 256, ATTN_SMEM>>>();

    // 3) output projection (A = g_AO rounded at write, W raw with B-frag cvt)
    gemm_mma<Dn, false>
        <<<dim3(Dn / 128, (Bn * Sn) / 128), 256, GEMM_SMEM>>>(
            ao_ptr, w_out, b_out, out);
}

// round 6
// speedup vs baseline: 5.9570x; 1.6936x over previous
#include <cuda_runtime.h>
#include <cuda_fp16.h>
#include <cstdint>

#define Bn 4
#define Sn 2048
#define Dn 768
#define Hn 12
#define HDn 64
// 0.125 * log2(e): folded into Q so softmax is pure ex2
#define QSCALE 0.1803368801111204f

// Scratch (allocation-free rule: __device__ globals). ~55MB total.
__device__ __half g_Q[Bn * Hn * Sn * HDn];   // pre-scaled by QSCALE
__device__ __half g_K[Bn * Hn * Sn * HDn];
__device__ __half g_V[Bn * Hn * Sn * HDn];
__device__ __half g_AO[Bn * Sn * Dn];        // phase 1: rounded x; phase 2: attn out
__device__ __half g_Wqkv_h[Dn * 3 * Dn];
__device__ __half g_Wout_h[Dn * Dn];

// ---------------------------------------------------------------------------
// Helpers (base sm_100: cp.async, fp16 mma.sync, ldmatrix)
// ---------------------------------------------------------------------------
__device__ __forceinline__ uint32_t smem_u32(const void* p) {
    uint32_t a;
    asm("{ .reg .u64 t; cvta.to.shared.u64 t, %1; cvt.u32.u64 %0, t; }"
        : "=r"(a) : "l"(p));
    return a;
}
__device__ __forceinline__ void cp16(const void* dst, const void* src) {
    asm volatile("cp.async.cg.shared.global [%0], [%1], 16;"
                 :: "r"(smem_u32(dst)), "l"(src));
}
__device__ __forceinline__ void cp_commit() {
    asm volatile("cp.async.commit_group;" ::: "memory");
}
template <int N>
__device__ __forceinline__ void cp_wait() {
    asm volatile("cp.async.wait_group %0;" :: "n"(N) : "memory");
}
__device__ __forceinline__ float ex2(float x) {
    float r;
    asm("ex2.approx.f32 %0, %1;" : "=f"(r) : "f"(x));
    return r;
}
// D(16x8,f32) += A(16x16,f16) * B(16x8,f16)
__device__ __forceinline__ void mma16(float* c, const uint32_t* a, const uint32_t* b) {
    asm volatile(
        "mma.sync.aligned.m16n8k16.row.col.f32.f16.f16.f32 "
        "{%0,%1,%2,%3}, {%4,%5,%6,%7}, {%8,%9}, {%0,%1,%2,%3};"
        : "+f"(c[0]), "+f"(c[1]), "+f"(c[2]), "+f"(c[3])
        : "r"(a[0]), "r"(a[1]), "r"(a[2]), "r"(a[3]), "r"(b[0]), "r"(b[1]));
}
__device__ __forceinline__ void ldsm_x4(uint32_t* r, uint32_t addr) {
    asm volatile("ldmatrix.sync.aligned.m8n8.x4.shared.b16 {%0,%1,%2,%3}, [%4];"
                 : "=r"(r[0]), "=r"(r[1]), "=r"(r[2]), "=r"(r[3]) : "r"(addr));
}
__device__ __forceinline__ void ldsm_x4_t(uint32_t* r, uint32_t addr) {
    asm volatile("ldmatrix.sync.aligned.m8n8.x4.trans.shared.b16 {%0,%1,%2,%3}, [%4];"
                 : "=r"(r[0]), "=r"(r[1]), "=r"(r[2]), "=r"(r[3]) : "r"(addr));
}

// ---------------------------------------------------------------------------
// Pre-pass: round fp32 -> fp16 (RN) elementwise
// ---------------------------------------------------------------------------
__global__ void round_h_kernel(const float4* __restrict__ src,
                               uint2* __restrict__ dst, int n4) {
    int i = blockIdx.x * blockDim.x + threadIdx.x;
    if (i >= n4) return;
    float4 v = src[i];
    __half2 lo = __floats2half2_rn(v.x, v.y);
    __half2 hi = __floats2half2_rn(v.z, v.w);
    uint2 o;
    o.x = *(uint32_t*)&lo;
    o.y = *(uint32_t*)&hi;
    dst[i] = o;
}

// ---------------------------------------------------------------------------
// fp16 mma GEMM: C[M,N] = A[M,768] @ W[768,N] + bias (A, W half; accum fp32)
// 128x128 tile, 256 threads, 8 warps (2x4), warp tile 64x32, mma m16n8k16.
// 4-stage cp.async pipeline, k-chunk 16. Fragments via ldmatrix.
// QKV=true : epilogue scatters half Q(+scale)/K/V into [B,H,S,HD]
// QKV=false: epilogue writes C = fp32 (+bias)
// ---------------------------------------------------------------------------
template <int N, bool QKV>
__global__ void __launch_bounds__(256) gemm_h(const __half* __restrict__ Ag,
                                              const __half* __restrict__ W,
                                              const float* __restrict__ bias,
                                              float* __restrict__ C) {
    __shared__ __half As[4][128][24];    // 16 + 8 pad (48B stride -> conflict-free)
    __shared__ __half Bs[4][16][136];    // 128 + 8 pad (272B stride)
    __shared__ float s_bias[128];

    const int tid = threadIdx.x;
    const int lane = tid & 31, warp = tid >> 5;
    const int g = lane >> 2, t = lane & 3;
    const int m0 = (warp >> 2) * 64, n0 = (warp & 3) * 32;
    const int bm = blockIdx.y * 128, bn = blockIdx.x * 128;

    if (tid < 128) s_bias[tid] = bias[bn + tid];

    const int arow = tid >> 1, ac8 = (tid & 1) * 8;
    const int brow = tid >> 4, bc8 = (tid & 15) * 8;
    auto load_stage = [&](int st, int k0) {
        cp16(&As[st][arow][ac8], Ag + (size_t)(bm + arow) * Dn + k0 + ac8);
        cp16(&Bs[st][brow][bc8], W + (size_t)(k0 + brow) * N + bn + bc8);
    };

    float acc[4][4][4];
#pragma unroll
    for (int a = 0; a < 4; a++)
#pragma unroll
        for (int b = 0; b < 4; b++)
#pragma unroll
            for (int c = 0; c < 4; c++) acc[a][b][c] = 0.f;

    load_stage(0, 0);  cp_commit();
    load_stage(1, 16); cp_commit();
    load_stage(2, 32); cp_commit();

    // per-lane ldmatrix row/col offsets
    const int lrA = lane & 15, lcA = (lane >> 4) * 8;     // A / x4
    const int lrB = lane & 15, lcB = (lane >> 4) * 8;     // B / x4.trans

    for (int ch = 0; ch < 48; ch++) {
        cp_wait<2>();
        __syncthreads();
        if (ch + 3 < 48) {
            load_stage((ch + 3) & 3, (ch + 3) * 16);
            cp_commit();
        }
        const int buf = ch & 3;
        uint32_t a[4][4];
#pragma unroll
        for (int mb = 0; mb < 4; mb++)
            ldsm_x4(a[mb], smem_u32(&As[buf][m0 + mb * 16 + lrA][lcA]));
#pragma unroll
        for (int p = 0; p < 2; p++) {
            uint32_t bq[4];
            ldsm_x4_t(bq, smem_u32(&Bs[buf][lrB][n0 + p * 16 + lcB]));
#pragma unroll
            for (int mb = 0; mb < 4; mb++) {
                mma16(acc[mb][2 * p], a[mb], bq);
                mma16(acc[mb][2 * p + 1], a[mb], bq + 2);
            }
        }
    }

    // Epilogue: c0/c1 -> row r0 cols 2t,2t+1 ; c2/c3 -> row r0+8
#pragma unroll
    for (int mb = 0; mb < 4; mb++) {
        const int row0 = bm + m0 + mb * 16 + g;
        const int row1 = row0 + 8;
#pragma unroll
        for (int nb = 0; nb < 4; nb++) {
            const int ci = n0 + nb * 8 + 2 * t;
            const int col0 = bn + ci;
            const float b0 = s_bias[ci], b1 = s_bias[ci + 1];
            if (QKV) {
                const int part = col0 / Dn;
                const int rem = col0 - part * Dn;
                const int hh = rem >> 6, d0 = rem & 63;
                const float mulv = (part == 0) ? QSCALE : 1.0f;
                __half2 v0 = __floats2half2_rn((acc[mb][nb][0] + b0) * mulv,
                                               (acc[mb][nb][1] + b1) * mulv);
                __half2 v1 = __floats2half2_rn((acc[mb][nb][2] + b0) * mulv,
                                               (acc[mb][nb][3] + b1) * mulv);
                __half* dst = (part == 0) ? g_Q : ((part == 1) ? g_K : g_V);
                size_t base0 =
                    (((size_t)((row0 >> 11) * Hn + hh) * Sn) + (row0 & 2047)) * HDn + d0;
                size_t base1 =
                    (((size_t)((row1 >> 11) * Hn + hh) * Sn) + (row1 & 2047)) * HDn + d0;
                *(__half2*)(dst + base0) = v0;
                *(__half2*)(dst + base1) = v1;
            } else {
                *(float2*)(C + (size_t)row0 * Dn + col0) =
                    make_float2(acc[mb][nb][0] + b0, acc[mb][nb][1] + b1);
                *(float2*)(C + (size_t)row1 * Dn + col0) =
                    make_float2(acc[mb][nb][2] + b0, acc[mb][nb][3] + b1);
            }
        }
    }
}

// ---------------------------------------------------------------------------
// Flash attention, fp16 mma m16n8k16, fp32 accum/softmax.
// BQ=256, BK=64, HD=64. 256 threads = 8 warps; warp owns 32 q rows.
// Q fragments hoisted (tile-invariant). K consumed natural [kc][d] via
// non-trans ldmatrix (= col-major B); V via trans ldmatrix; P stored half2.
// K/V double-buffered cp.async. Softmax base-2 (scale folded into Q).
// ---------------------------------------------------------------------------
#define ATTN_SMEM ((256 * 72 + 128 * 72 + 128 * 72 + 256 * 72) * 2)

__global__ void __launch_bounds__(256) attn_kernel() {
    extern __shared__ __half sm[];
    __half(*Qs)[72] = (__half(*)[72])sm;                       // [256][72]
    __half(*Ks)[72] = (__half(*)[72])(sm + 256 * 72);          // [2*64][72]
    __half(*Vs)[72] = (__half(*)[72])(sm + 384 * 72);          // [2*64][72]
    __half(*Ps)[72] = (__half(*)[72])(sm + 512 * 72);          // [256][72]

    const int tid = threadIdx.x;
    const int lane = tid & 31, warp = tid >> 5;
    const int g = lane >> 2, t = lane & 3;
    const int q0 = warp * 32;

    const int b = blockIdx.z, h = blockIdx.y, qt = blockIdx.x;
    const __half* Qg = g_Q + ((size_t)(b * Hn + h) * Sn + qt * 256) * HDn;
    const __half* Kg = g_K + (size_t)(b * Hn + h) * Sn * HDn;
    const __half* Vg = g_V + (size_t)(b * Hn + h) * Sn * HDn;

    auto load_kv = [&](int st, int kt2) {
        const __half* Kp = Kg + (size_t)kt2 * 64 * 64;
        const __half* Vp = Vg + (size_t)kt2 * 64 * 64;
#pragma unroll
        for (int i = 0; i < 2; i++) {
            int lin = tid + i * 256;
            int r = lin >> 3, c8 = (lin & 7) * 8;
            cp16(&Ks[st * 64 + r][c8], Kp + r * 64 + c8);
            cp16(&Vs[st * 64 + r][c8], Vp + r * 64 + c8);
        }
    };

    // Q tile 256x64
#pragma unroll
    for (int i = 0; i < 8; i++) {
        int lin = tid + i * 256;
        int r = lin >> 3, c8 = (lin & 7) * 8;
        cp16(&Qs[r][c8], Qg + r * 64 + c8);
    }
    load_kv(0, 0);
    cp_commit();
    cp_wait<0>();
    __syncthreads();

    // Hoist Q fragments: tile-invariant across all 32 kv tiles
    const int lr = lane & 15, lc = (lane >> 4) * 8;
    uint32_t qa[4][2][4];
#pragma unroll
    for (int ks = 0; ks < 4; ks++)
#pragma unroll
        for (int mb = 0; mb < 2; mb++)
            ldsm_x4(qa[ks][mb], smem_u32(&Qs[q0 + mb * 16 + lr][ks * 16 + lc]));

    float m_[2][2], l_[2][2], oa[2][8][4];
#pragma unroll
    for (int mb = 0; mb < 2; mb++)
#pragma unroll
        for (int hf = 0; hf < 2; hf++) {
            m_[mb][hf] = -1e30f;
            l_[mb][hf] = 0.f;
        }
#pragma unroll
    for (int mb = 0; mb < 2; mb++)
#pragma unroll
        for (int nb = 0; nb < 8; nb++)
#pragma unroll
            for (int c = 0; c < 4; c++) oa[mb][nb][c] = 0.f;

    // K non-trans x4 per-lane offsets: rows n, cols k
    const int krow = ((lane >> 4) << 3) + (lane & 7);    // n within 16-block
    const int kcol = ((lane >> 3) & 1) * 8;              // k half-block

    for (int kt = 0; kt < 32; kt++) {
        if (kt + 1 < 32) {
            load_kv((kt + 1) & 1, kt + 1);
            cp_commit();
        }
        const int kb = (kt & 1) * 64;

        // ---- S = Q' @ K^T ----
        float sf[2][8][4];
#pragma unroll
        for (int mb = 0; mb < 2; mb++)
#pragma unroll
            for (int nb = 0; nb < 8; nb++)
#pragma unroll
                for (int c = 0; c < 4; c++) sf[mb][nb][c] = 0.f;

#pragma unroll
        for (int ks = 0; ks < 4; ks++) {
#pragma unroll
            for (int np = 0; np < 4; np++) {
                uint32_t kq[4];
                ldsm_x4(kq, smem_u32(&Ks[kb + np * 16 + krow][ks * 16 + kcol]));
#pragma unroll
                for (int mb = 0; mb < 2; mb++) {
                    mma16(sf[mb][2 * np], qa[ks][mb], kq);
                    mma16(sf[mb][2 * np + 1], qa[ks][mb], kq + 2);
                }
            }
        }

        // ---- online softmax, base 2 ----
#pragma unroll
        for (int mb = 0; mb < 2; mb++)
#pragma unroll
            for (int hf = 0; hf < 2; hf++) {
                float rmax = -1e30f;
#pragma unroll
                for (int nb = 0; nb < 8; nb++) {
                    rmax = fmaxf(rmax, sf[mb][nb][2 * hf]);
                    rmax = fmaxf(rmax, sf[mb][nb][2 * hf + 1]);
                }
                rmax = fmaxf(rmax, __shfl_xor_sync(0xffffffffu, rmax, 1));
                rmax = fmaxf(rmax, __shfl_xor_sync(0xffffffffu, rmax, 2));
                const float mn = fmaxf(m_[mb][hf], rmax);
                const float corr = ex2(m_[mb][hf] - mn);
                m_[mb][hf] = mn;
                float rs = 0.f;
                const int row = q0 + mb * 16 + g + 8 * hf;
#pragma unroll
                for (int nb = 0; nb < 8; nb++) {
                    float p0 = ex2(sf[mb][nb][2 * hf] - mn);
                    float p1 = ex2(sf[mb][nb][2 * hf + 1] - mn);
                    rs += p0 + p1;
                    *(__half2*)&Ps[row][nb * 8 + 2 * t] = __floats2half2_rn(p0, p1);
                }
                rs += __shfl_xor_sync(0xffffffffu, rs, 1);
                rs += __shfl_xor_sync(0xffffffffu, rs, 2);
                l_[mb][hf] = l_[mb][hf] * corr + rs;
#pragma unroll
                for (int nb = 0; nb < 8; nb++) {
                    oa[mb][nb][2 * hf] *= corr;
                    oa[mb][nb][2 * hf + 1] *= corr;
                }
            }
        __syncwarp();   // P rows produced+consumed within one warp

        // ---- O += P @ V ----
#pragma unroll
        for (int ks = 0; ks < 4; ks++) {
            uint32_t pa[2][4];
#pragma unroll
            for (int mb = 0; mb < 2; mb++)
                ldsm_x4(pa[mb], smem_u32(&Ps[q0 + mb * 16 + lr][ks * 16 + lc]));
#pragma unroll
            for (int np = 0; np < 4; np++) {
                uint32_t vq[4];
                ldsm_x4_t(vq, smem_u32(&Vs[kb + ks * 16 + lr][np * 16 + lc]));
#pragma unroll
                for (int mb = 0; mb < 2; mb++) {
                    mma16(oa[mb][2 * np], pa[mb], vq);
                    mma16(oa[mb][2 * np + 1], pa[mb], vq + 2);
                }
            }
        }
        cp_wait<0>();     // next tile resident
        __syncthreads();  // all warps done before next prefetch overwrites
    }

    // normalize + write half to g_AO [B,S,H*HD]
#pragma unroll
    for (int mb = 0; mb < 2; mb++)
#pragma unroll
        for (int hf = 0; hf < 2; hf++) {
            const int q = qt * 256 + q0 + mb * 16 + g + 8 * hf;
            const float inv = 1.0f / l_[mb][hf];
            __half* dst = g_AO + ((size_t)(b * Sn + q)) * Dn + h * 64;
#pragma unroll
            for (int nb = 0; nb < 8; nb++) {
                *(__half2*)(dst + nb * 8 + 2 * t) =
                    __floats2half2_rn(oa[mb][nb][2 * hf] * inv,
                                      oa[mb][nb][2 * hf + 1] * inv);
            }
        }
}

// ---------------------------------------------------------------------------
extern "C" void kernel_launch(void* const* d_in, const int* in_sizes, int n_in,
                              void* d_out, int out_size)
{
    const float* x     = (const float*)d_in[0];
    const float* w_qkv = (const float*)d_in[1];
    const float* b_qkv = (const float*)d_in[2];
    const float* w_out = (const float*)d_in[3];
    const float* b_out = (const float*)d_in[4];
    float* out = (float*)d_out;

    (void)in_sizes; (void)n_in; (void)out_size;

    static bool init_done = false;
    static __half *ao_ptr, *wqkv_ptr, *wout_ptr;
    if (!init_done) {
        cudaGetSymbolAddress((void**)&ao_ptr, g_AO);
        cudaGetSymbolAddress((void**)&wqkv_ptr, g_Wqkv_h);
        cudaGetSymbolAddress((void**)&wout_ptr, g_Wout_h);
        cudaFuncSetAttribute(attn_kernel,
                             cudaFuncAttributeMaxDynamicSharedMemorySize, ATTN_SMEM);
        init_done = true;
    }

    // 0) round inputs to fp16 (x lands in g_AO, dead until attention)
    {
        const int n4x = Bn * Sn * Dn / 4;
        const int n4q = Dn * 3 * Dn / 4;
        const int n4o = Dn * Dn / 4;
        round_h_kernel<<<(n4x + 255) / 256, 256>>>((const float4*)x, (uint2*)ao_ptr, n4x);
        round_h_kernel<<<(n4q + 255) / 256, 256>>>((const float4*)w_qkv, (uint2*)wqkv_ptr, n4q);
        round_h_kernel<<<(n4o + 255) / 256, 256>>>((const float4*)w_out, (uint2*)wout_ptr, n4o);
    }

    // 1) fused QKV projection -> half Q(scaled)/K/V in [B,H,S,HD]
    gemm_h<3 * Dn, true><<<dim3((3 * Dn) / 128, (Bn * Sn) / 128), 256>>>(
        ao_ptr, wqkv_ptr, b_qkv, nullptr);

    // 2) flash attention (overwrites g_AO with half attention output)
    attn_kernel<<<dim3(Sn / 256, Hn, Bn), 256, ATTN_SMEM>>>();

    // 3) output projection -> fp32 out
    gemm_h<Dn, false><<<dim3(Dn / 128, (Bn * Sn) / 128), 256>>>(
        ao_ptr, wout_ptr, b_out, out);
}

// round 7
// speedup vs baseline: 6.9010x; 1.1585x over previous
#include <cuda_runtime.h>
#include <cuda_fp16.h>
#include <cstdint>

#define Bn 4
#define Sn 2048
#define Dn 768
#define Hn 12
#define HDn 64
// 0.125 * log2(e): folded into Q so softmax is pure ex2
#define QSCALE 0.1803368801111204f

// Scratch (allocation-free rule: __device__ globals). ~55MB total.
__device__ __half g_Q[Bn * Hn * Sn * HDn];   // pre-scaled by QSCALE
__device__ __half g_K[Bn * Hn * Sn * HDn];
__device__ __half g_V[Bn * Hn * Sn * HDn];
__device__ __half g_AO[Bn * Sn * Dn];        // phase 1: rounded x; phase 2: attn out
__device__ __half g_Wqkv_h[Dn * 3 * Dn];
__device__ __half g_Wout_h[Dn * Dn];

// ---------------------------------------------------------------------------
// Helpers (base sm_100: cp.async, fp16 mma.sync, ldmatrix)
// ---------------------------------------------------------------------------
__device__ __forceinline__ uint32_t smem_u32(const void* p) {
    uint32_t a;
    asm("{ .reg .u64 t; cvta.to.shared.u64 t, %1; cvt.u32.u64 %0, t; }"
        : "=r"(a) : "l"(p));
    return a;
}
__device__ __forceinline__ void cp16(const void* dst, const void* src) {
    asm volatile("cp.async.cg.shared.global [%0], [%1], 16;"
                 :: "r"(smem_u32(dst)), "l"(src));
}
__device__ __forceinline__ void cp_commit() {
    asm volatile("cp.async.commit_group;" ::: "memory");
}
template <int N>
__device__ __forceinline__ void cp_wait() {
    asm volatile("cp.async.wait_group %0;" :: "n"(N) : "memory");
}
__device__ __forceinline__ float ex2(float x) {
    float r;
    asm("ex2.approx.f32 %0, %1;" : "=f"(r) : "f"(x));
    return r;
}
__device__ __forceinline__ uint32_t packh2(float a, float b) {
    __half2 h = __floats2half2_rn(a, b);
    return *(uint32_t*)&h;
}
// D(16x8,f32) += A(16x16,f16) * B(16x8,f16)
__device__ __forceinline__ void mma16(float* c, const uint32_t* a, const uint32_t* b) {
    asm volatile(
        "mma.sync.aligned.m16n8k16.row.col.f32.f16.f16.f32 "
        "{%0,%1,%2,%3}, {%4,%5,%6,%7}, {%8,%9}, {%0,%1,%2,%3};"
        : "+f"(c[0]), "+f"(c[1]), "+f"(c[2]), "+f"(c[3])
        : "r"(a[0]), "r"(a[1]), "r"(a[2]), "r"(a[3]), "r"(b[0]), "r"(b[1]));
}
__device__ __forceinline__ void ldsm_x4(uint32_t* r, uint32_t addr) {
    asm volatile("ldmatrix.sync.aligned.m8n8.x4.shared.b16 {%0,%1,%2,%3}, [%4];"
                 : "=r"(r[0]), "=r"(r[1]), "=r"(r[2]), "=r"(r[3]) : "r"(addr));
}
__device__ __forceinline__ void ldsm_x4_t(uint32_t* r, uint32_t addr) {
    asm volatile("ldmatrix.sync.aligned.m8n8.x4.trans.shared.b16 {%0,%1,%2,%3}, [%4];"
                 : "=r"(r[0]), "=r"(r[1]), "=r"(r[2]), "=r"(r[3]) : "r"(addr));
}

// ---------------------------------------------------------------------------
// Pre-pass: round fp32 -> fp16 (RN) elementwise
// ---------------------------------------------------------------------------
__global__ void round_h_kernel(const float4* __restrict__ src,
                               uint2* __restrict__ dst, int n4) {
    int i = blockIdx.x * blockDim.x + threadIdx.x;
    if (i >= n4) return;
    float4 v = src[i];
    uint2 o;
    o.x = packh2(v.x, v.y);
    o.y = packh2(v.z, v.w);
    dst[i] = o;
}

// ---------------------------------------------------------------------------
// fp16 mma GEMM: C[M,N] = A[M,768] @ W[768,N] + bias (A, W half; accum fp32)
// 128x128 tile, 256 threads, 8 warps (2x4), warp tile 64x32, mma m16n8k16.
// 4-stage cp.async pipeline, k-chunk 16. Fragments via ldmatrix.
// __launch_bounds__(256,2): cap regs at 128 -> 2 CTAs/SM (cross-CTA overlap).
// ---------------------------------------------------------------------------
template <int N, bool QKV>
__global__ void __launch_bounds__(256, 2) gemm_h(const __half* __restrict__ Ag,
                                                 const __half* __restrict__ W,
                                                 const float* __restrict__ bias,
                                                 float* __restrict__ C) {
    __shared__ __half As[4][128][24];    // 16 + 8 pad
    __shared__ __half Bs[4][16][136];    // 128 + 8 pad
    __shared__ float s_bias[128];

    const int tid = threadIdx.x;
    const int lane = tid & 31, warp = tid >> 5;
    const int g = lane >> 2, t = lane & 3;
    const int m0 = (warp >> 2) * 64, n0 = (warp & 3) * 32;
    const int bm = blockIdx.y * 128, bn = blockIdx.x * 128;

    if (tid < 128) s_bias[tid] = bias[bn + tid];

    const int arow = tid >> 1, ac8 = (tid & 1) * 8;
    const int brow = tid >> 4, bc8 = (tid & 15) * 8;
    auto load_stage = [&](int st, int k0) {
        cp16(&As[st][arow][ac8], Ag + (size_t)(bm + arow) * Dn + k0 + ac8);
        cp16(&Bs[st][brow][bc8], W + (size_t)(k0 + brow) * N + bn + bc8);
    };

    float acc[4][4][4];
#pragma unroll
    for (int a = 0; a < 4; a++)
#pragma unroll
        for (int b = 0; b < 4; b++)
#pragma unroll
            for (int c = 0; c < 4; c++) acc[a][b][c] = 0.f;

    load_stage(0, 0);  cp_commit();
    load_stage(1, 16); cp_commit();
    load_stage(2, 32); cp_commit();

    const int lrA = lane & 15, lcA = (lane >> 4) * 8;
    const int lrB = lane & 15, lcB = (lane >> 4) * 8;

    for (int ch = 0; ch < 48; ch++) {
        cp_wait<2>();
        __syncthreads();
        if (ch + 3 < 48) {
            load_stage((ch + 3) & 3, (ch + 3) * 16);
            cp_commit();
        }
        const int buf = ch & 3;
        uint32_t a[4][4];
#pragma unroll
        for (int mb = 0; mb < 4; mb++)
            ldsm_x4(a[mb], smem_u32(&As[buf][m0 + mb * 16 + lrA][lcA]));
#pragma unroll
        for (int p = 0; p < 2; p++) {
            uint32_t bq[4];
            ldsm_x4_t(bq, smem_u32(&Bs[buf][lrB][n0 + p * 16 + lcB]));
#pragma unroll
            for (int mb = 0; mb < 4; mb++) {
                mma16(acc[mb][2 * p], a[mb], bq);
                mma16(acc[mb][2 * p + 1], a[mb], bq + 2);
            }
        }
    }

    // Epilogue
#pragma unroll
    for (int mb = 0; mb < 4; mb++) {
        const int row0 = bm + m0 + mb * 16 + g;
        const int row1 = row0 + 8;
#pragma unroll
        for (int nb = 0; nb < 4; nb++) {
            const int ci = n0 + nb * 8 + 2 * t;
            const int col0 = bn + ci;
            const float b0 = s_bias[ci], b1 = s_bias[ci + 1];
            if (QKV) {
                const int part = col0 / Dn;
                const int rem = col0 - part * Dn;
                const int hh = rem >> 6, d0 = rem & 63;
                const float mulv = (part == 0) ? QSCALE : 1.0f;
                __half2 v0 = __floats2half2_rn((acc[mb][nb][0] + b0) * mulv,
                                               (acc[mb][nb][1] + b1) * mulv);
                __half2 v1 = __floats2half2_rn((acc[mb][nb][2] + b0) * mulv,
                                               (acc[mb][nb][3] + b1) * mulv);
                __half* dst = (part == 0) ? g_Q : ((part == 1) ? g_K : g_V);
                size_t base0 =
                    (((size_t)((row0 >> 11) * Hn + hh) * Sn) + (row0 & 2047)) * HDn + d0;
                size_t base1 =
                    (((size_t)((row1 >> 11) * Hn + hh) * Sn) + (row1 & 2047)) * HDn + d0;
                *(__half2*)(dst + base0) = v0;
                *(__half2*)(dst + base1) = v1;
            } else {
                *(float2*)(C + (size_t)row0 * Dn + col0) =
                    make_float2(acc[mb][nb][0] + b0, acc[mb][nb][1] + b1);
                *(float2*)(C + (size_t)row1 * Dn + col0) =
                    make_float2(acc[mb][nb][2] + b0, acc[mb][nb][3] + b1);
            }
        }
    }
}

// ---------------------------------------------------------------------------
// Flash attention, fp16 mma m16n8k16, fp32 accum/softmax.
// BQ=256, BK=64, HD=64. 256 threads = 8 warps; warp owns 32 q rows.
// Q fragments hoisted. K via non-trans ldmatrix (natural [kc][d] = col-major B).
// P stays in REGISTERS: the S-accum fragment layout == mma-A fragment layout
// over kc, so exp'd scores pack directly into A fragments (no smem round-trip).
// V via trans ldmatrix. K/V double-buffered cp.async. Softmax base-2.
// ---------------------------------------------------------------------------
#define ATTN_SMEM ((256 * 72 + 128 * 72 + 128 * 72) * 2)

__global__ void __launch_bounds__(256) attn_kernel() {
    extern __shared__ __half sm[];
    __half(*Qs)[72] = (__half(*)[72])sm;                       // [256][72]
    __half(*Ks)[72] = (__half(*)[72])(sm + 256 * 72);          // [2*64][72]
    __half(*Vs)[72] = (__half(*)[72])(sm + 384 * 72);          // [2*64][72]

    const int tid = threadIdx.x;
    const int lane = tid & 31, warp = tid >> 5;
    const int g = lane >> 2, t = lane & 3;
    const int q0 = warp * 32;

    const int b = blockIdx.z, h = blockIdx.y, qt = blockIdx.x;
    const __half* Qg = g_Q + ((size_t)(b * Hn + h) * Sn + qt * 256) * HDn;
    const __half* Kg = g_K + (size_t)(b * Hn + h) * Sn * HDn;
    const __half* Vg = g_V + (size_t)(b * Hn + h) * Sn * HDn;

    auto load_kv = [&](int st, int kt2) {
        const __half* Kp = Kg + (size_t)kt2 * 64 * 64;
        const __half* Vp = Vg + (size_t)kt2 * 64 * 64;
#pragma unroll
        for (int i = 0; i < 2; i++) {
            int lin = tid + i * 256;
            int r = lin >> 3, c8 = (lin & 7) * 8;
            cp16(&Ks[st * 64 + r][c8], Kp + r * 64 + c8);
            cp16(&Vs[st * 64 + r][c8], Vp + r * 64 + c8);
        }
    };

    // Q tile 256x64
#pragma unroll
    for (int i = 0; i < 8; i++) {
        int lin = tid + i * 256;
        int r = lin >> 3, c8 = (lin & 7) * 8;
        cp16(&Qs[r][c8], Qg + r * 64 + c8);
    }
    load_kv(0, 0);
    cp_commit();
    cp_wait<0>();
    __syncthreads();

    // Hoist Q fragments (tile-invariant)
    const int lr = lane & 15, lc = (lane >> 4) * 8;
    uint32_t qa[4][2][4];
#pragma unroll
    for (int ks = 0; ks < 4; ks++)
#pragma unroll
        for (int mb = 0; mb < 2; mb++)
            ldsm_x4(qa[ks][mb], smem_u32(&Qs[q0 + mb * 16 + lr][ks * 16 + lc]));

    float m_[2][2], l_[2][2], oa[2][8][4];
#pragma unroll
    for (int mb = 0; mb < 2; mb++)
#pragma unroll
        for (int hf = 0; hf < 2; hf++) {
            m_[mb][hf] = -1e30f;
            l_[mb][hf] = 0.f;
        }
#pragma unroll
    for (int mb = 0; mb < 2; mb++)
#pragma unroll
        for (int nb = 0; nb < 8; nb++)
#pragma unroll
            for (int c = 0; c < 4; c++) oa[mb][nb][c] = 0.f;

    // K non-trans x4 per-lane offsets: rows n, cols k
    const int krow = ((lane >> 4) << 3) + (lane & 7);
    const int kcol = ((lane >> 3) & 1) * 8;

    for (int kt = 0; kt < 32; kt++) {
        if (kt + 1 < 32) {
            load_kv((kt + 1) & 1, kt + 1);
            cp_commit();
        }
        const int kb = (kt & 1) * 64;

        // ---- S = Q' @ K^T ----
        float sf[2][8][4];
#pragma unroll
        for (int mb = 0; mb < 2; mb++)
#pragma unroll
            for (int nb = 0; nb < 8; nb++)
#pragma unroll
                for (int c = 0; c < 4; c++) sf[mb][nb][c] = 0.f;

#pragma unroll
        for (int ks = 0; ks < 4; ks++) {
#pragma unroll
            for (int np = 0; np < 4; np++) {
                uint32_t kq[4];
                ldsm_x4(kq, smem_u32(&Ks[kb + np * 16 + krow][ks * 16 + kcol]));
#pragma unroll
                for (int mb = 0; mb < 2; mb++) {
                    mma16(sf[mb][2 * np], qa[ks][mb], kq);
                    mma16(sf[mb][2 * np + 1], qa[ks][mb], kq + 2);
                }
            }
        }

        // ---- online softmax, base 2; exp'd P left in sf registers ----
#pragma unroll
        for (int mb = 0; mb < 2; mb++)
#pragma unroll
            for (int hf = 0; hf < 2; hf++) {
                float rmax = -1e30f;
#pragma unroll
                for (int nb = 0; nb < 8; nb++) {
                    rmax = fmaxf(rmax, sf[mb][nb][2 * hf]);
                    rmax = fmaxf(rmax, sf[mb][nb][2 * hf + 1]);
                }
                rmax = fmaxf(rmax, __shfl_xor_sync(0xffffffffu, rmax, 1));
                rmax = fmaxf(rmax, __shfl_xor_sync(0xffffffffu, rmax, 2));
                const float mn = fmaxf(m_[mb][hf], rmax);
                const float corr = ex2(m_[mb][hf] - mn);
                m_[mb][hf] = mn;
                float rs = 0.f;
#pragma unroll
                for (int nb = 0; nb < 8; nb++) {
                    float p0 = ex2(sf[mb][nb][2 * hf] - mn);
                    float p1 = ex2(sf[mb][nb][2 * hf + 1] - mn);
                    sf[mb][nb][2 * hf] = p0;
                    sf[mb][nb][2 * hf + 1] = p1;
                    rs += p0 + p1;
                }
                rs += __shfl_xor_sync(0xffffffffu, rs, 1);
                rs += __shfl_xor_sync(0xffffffffu, rs, 2);
                l_[mb][hf] = l_[mb][hf] * corr + rs;
#pragma unroll
                for (int nb = 0; nb < 8; nb++) {
                    oa[mb][nb][2 * hf] *= corr;
                    oa[mb][nb][2 * hf + 1] *= corr;
                }
            }

        // ---- O += P @ V  (P packed from sf registers; no smem) ----
#pragma unroll
        for (int ks = 0; ks < 4; ks++) {
            uint32_t pa[2][4];
#pragma unroll
            for (int mb = 0; mb < 2; mb++) {
                pa[mb][0] = packh2(sf[mb][2 * ks][0], sf[mb][2 * ks][1]);
                pa[mb][1] = packh2(sf[mb][2 * ks][2], sf[mb][2 * ks][3]);
                pa[mb][2] = packh2(sf[mb][2 * ks + 1][0], sf[mb][2 * ks + 1][1]);
                pa[mb][3] = packh2(sf[mb][2 * ks + 1][2], sf[mb][2 * ks + 1][3]);
            }
#pragma unroll
            for (int np = 0; np < 4; np++) {
                uint32_t vq[4];
                ldsm_x4_t(vq, smem_u32(&Vs[kb + ks * 16 + lr][np * 16 + lc]));
#pragma unroll
                for (int mb = 0; mb < 2; mb++) {
                    mma16(oa[mb][2 * np], pa[mb], vq);
                    mma16(oa[mb][2 * np + 1], pa[mb], vq + 2);
                }
            }
        }
        cp_wait<0>();     // next tile resident
        __syncthreads();  // all warps done before next prefetch overwrites
    }

    // normalize + write half to g_AO [B,S,H*HD]
#pragma unroll
    for (int mb = 0; mb < 2; mb++)
#pragma unroll
        for (int hf = 0; hf < 2; hf++) {
            const int q = qt * 256 + q0 + mb * 16 + g + 8 * hf;
            const float inv = 1.0f / l_[mb][hf];
            __half* dst = g_AO + ((size_t)(b * Sn + q)) * Dn + h * 64;
#pragma unroll
            for (int nb = 0; nb < 8; nb++) {
                *(__half2*)(dst + nb * 8 + 2 * t) =
                    __floats2half2_rn(oa[mb][nb][2 * hf] * inv,
                                      oa[mb][nb][2 * hf + 1] * inv);
            }
        }
}

// ---------------------------------------------------------------------------
extern "C" void kernel_launch(void* const* d_in, const int* in_sizes, int n_in,
                              void* d_out, int out_size)
{
    const float* x     = (const float*)d_in[0];
    const float* w_qkv = (const float*)d_in[1];
    const float* b_qkv = (const float*)d_in[2];
    const float* w_out = (const float*)d_in[3];
    const float* b_out = (const float*)d_in[4];
    float* out = (float*)d_out;

    (void)in_sizes; (void)n_in; (void)out_size;

    static bool init_done = false;
    static __half *ao_ptr, *wqkv_ptr, *wout_ptr;
    if (!init_done) {
        cudaGetSymbolAddress((void**)&ao_ptr, g_AO);
        cudaGetSymbolAddress((void**)&wqkv_ptr, g_Wqkv_h);
        cudaGetSymbolAddress((void**)&wout_ptr, g_Wout_h);
        cudaFuncSetAttribute(attn_kernel,
                             cudaFuncAttributeMaxDynamicSharedMemorySize, ATTN_SMEM);
        init_done = true;
    }

    // 0) round inputs to fp16 (x lands in g_AO, dead until attention)
    {
        const int n4x = Bn * Sn * Dn / 4;
        const int n4q = Dn * 3 * Dn / 4;
        const int n4o = Dn * Dn / 4;
        round_h_kernel<<<(n4x + 255) / 256, 256>>>((const float4*)x, (uint2*)ao_ptr, n4x);
        round_h_kernel<<<(n4q + 255) / 256, 256>>>((const float4*)w_qkv, (uint2*)wqkv_ptr, n4q);
        round_h_kernel<<<(n4o + 255) / 256, 256>>>((const float4*)w_out, (uint2*)wout_ptr, n4o);
    }

    // 1) fused QKV projection -> half Q(scaled)/K/V in [B,H,S,HD]
    gemm_h<3 * Dn, true><<<dim3((3 * Dn) / 128, (Bn * Sn) / 128), 256>>>(
        ao_ptr, wqkv_ptr, b_qkv, nullptr);

    // 2) flash attention (overwrites g_AO with half attention output)
    attn_kernel<<<dim3(Sn / 256, Hn, Bn), 256, ATTN_SMEM>>>();

    // 3) output projection -> fp32 out
    gemm_h<Dn, false><<<dim3(Dn / 128, (Bn * Sn) / 128), 256>>>(
        ao_ptr, wout_ptr, b_out, out);
}